// round 1
// baseline (speedup 1.0000x reference)
#include <cuda_runtime.h>
#include <cuda_bf16.h>
#include <cstdint>

#define NSONGS 100000
#define EMBED  64
#define BATCH  1024
#define SEQ    200

#define BM 128
#define BN 128
#define LDT 72   // smem row pitch in bf16 elems (144B) -> conflict-free ldmatrix

// Scratch (no allocations allowed): bf16 W (12.8MB) + bf16 pooled (128KB)
__device__ __nv_bfloat16 g_Wb[(size_t)NSONGS * EMBED];
__device__ __nv_bfloat16 g_pooled[BATCH * EMBED];

// ---------------------------------------------------------------------------
// Kernel 1: masked mean pooling. block = (64, 4): 4 samples/block, 64 dims.
// ---------------------------------------------------------------------------
__global__ void pool_kernel(const int* __restrict__ songs,
                            const float* __restrict__ emb) {
    __shared__ int s_ids[4][SEQ];
    __shared__ int s_cnt[4];
    const int ty = threadIdx.y;
    const int d  = threadIdx.x;
    const int row = blockIdx.x * 4 + ty;

    if (d == 0) s_cnt[ty] = 0;
    __syncthreads();

    const int* srow = songs + row * SEQ;
    int cnt = 0;
    for (int j = d; j < SEQ; j += 64) {
        int id = srow[j];
        s_ids[ty][j] = id;
        if (id != NSONGS) cnt++;
    }
    int wsum = __reduce_add_sync(0xffffffffu, cnt);
    if ((d & 31) == 0) atomicAdd(&s_cnt[ty], wsum);
    __syncthreads();

    float acc = 0.f;
    #pragma unroll 4
    for (int j = 0; j < SEQ; j++) {
        int id = s_ids[ty][j];
        if (id != NSONGS)
            acc += __ldg(&emb[(size_t)id * EMBED + d]);
    }
    float inv = 1.0f / (float)s_cnt[ty];
    g_pooled[row * EMBED + d] = __float2bfloat16(acc * inv);
}

// ---------------------------------------------------------------------------
// Kernel 2: W fp32 -> bf16
// ---------------------------------------------------------------------------
__global__ void convert_w_kernel(const float* __restrict__ W) {
    size_t i = (size_t)blockIdx.x * blockDim.x + threadIdx.x;
    size_t idx = i * 4;
    if (idx < (size_t)NSONGS * EMBED) {
        float4 v = *(const float4*)(W + idx);
        __nv_bfloat162 p0 = __floats2bfloat162_rn(v.x, v.y);
        __nv_bfloat162 p1 = __floats2bfloat162_rn(v.z, v.w);
        uint2 o;
        o.x = *(unsigned int*)&p0;
        o.y = *(unsigned int*)&p1;
        *(uint2*)(g_Wb + idx) = o;
    }
}

// ---------------------------------------------------------------------------
// Kernel 3: GEMM [1024,64]x[64,100000] bf16 mma + bias + poly sigmoid
// ---------------------------------------------------------------------------
__device__ __forceinline__ uint32_t s2u(const void* p) {
    return (uint32_t)__cvta_generic_to_shared(p);
}

__device__ __forceinline__ void ldsm_x4(uint32_t& r0, uint32_t& r1,
                                        uint32_t& r2, uint32_t& r3,
                                        uint32_t addr) {
    asm volatile("ldmatrix.sync.aligned.m8n8.x4.shared.b16 {%0,%1,%2,%3}, [%4];"
                 : "=r"(r0), "=r"(r1), "=r"(r2), "=r"(r3) : "r"(addr));
}

__device__ __forceinline__ void mma_16816(float* c, const uint32_t* a,
                                          const uint32_t* b) {
    asm volatile(
        "mma.sync.aligned.m16n8k16.row.col.f32.bf16.bf16.f32 "
        "{%0,%1,%2,%3},{%4,%5,%6,%7},{%8,%9},{%0,%1,%2,%3};"
        : "+f"(c[0]), "+f"(c[1]), "+f"(c[2]), "+f"(c[3])
        : "r"(a[0]), "r"(a[1]), "r"(a[2]), "r"(a[3]), "r"(b[0]), "r"(b[1]));
}

// Poly sigmoid: 1/2 + x/4 - x^3/48 + x^5/480 - 17x^7/80640, |err|<3e-5 on |x|<=1.
__device__ __forceinline__ float sigmoid_fast(float x) {
    float ax = fabsf(x);
    if (ax < 1.0f) {
        float x2 = x * x;
        return 0.5f + x * (0.25f + x2 * (-2.0833334e-2f +
                     x2 * (2.0833333e-3f + x2 * (-2.1081349e-4f))));
    }
    return 1.0f / (1.0f + __expf(-x));
}

__global__ __launch_bounds__(256) void gemm_kernel(const float* __restrict__ bias,
                                                   float* __restrict__ out) {
    __shared__ __nv_bfloat16 sA[BM * LDT];
    __shared__ __nv_bfloat16 sB[BN * LDT];

    const int tid = threadIdx.x;
    const int m0 = blockIdx.x * BM;
    const int n0 = blockIdx.y * BN;

    // Cooperative loads: each thread moves 4x 16B chunks for A and B.
    {
        int r = tid >> 3;          // 0..31
        int c = (tid & 7) * 8;     // 0..56 (bf16 elems)
        #pragma unroll
        for (int i = 0; i < 4; i++) {
            int row = r + i * 32;
            uint4 v = *(const uint4*)(g_pooled + (m0 + row) * EMBED + c);
            *(uint4*)(sA + row * LDT + c) = v;
        }
        #pragma unroll
        for (int i = 0; i < 4; i++) {
            int row = r + i * 32;
            int n = n0 + row;
            uint4 v = make_uint4(0u, 0u, 0u, 0u);
            if (n < NSONGS)
                v = *(const uint4*)(g_Wb + (size_t)n * EMBED + c);
            *(uint4*)(sB + row * LDT + c) = v;
        }
    }
    __syncthreads();

    const int warp = tid >> 5;
    const int lane = tid & 31;
    const int wm = (warp >> 2) * 64;   // 0 or 64
    const int wn = (warp & 3) * 32;    // 0,32,64,96

    float acc[4][4][4];
    #pragma unroll
    for (int mf = 0; mf < 4; mf++)
        #pragma unroll
        for (int nf = 0; nf < 4; nf++)
            #pragma unroll
            for (int i = 0; i < 4; i++) acc[mf][nf][i] = 0.f;

    // Per-lane ldmatrix address components
    const int a_row_in = (lane & 7) + ((lane >> 3) & 1) * 8; // row within 16
    const int a_col_in = (lane >> 4) * 8;                    // 0 or 8
    const int b_g = lane >> 3;
    const int b_row_in = (lane & 7) + (b_g >> 1) * 8;
    const int b_col_in = (b_g & 1) * 8;

    #pragma unroll
    for (int ks = 0; ks < 4; ks++) {
        const int kc = ks * 16;
        uint32_t af[4][4];
        #pragma unroll
        for (int mf = 0; mf < 4; mf++) {
            uint32_t addr = s2u(sA + (wm + mf * 16 + a_row_in) * LDT + kc + a_col_in);
            ldsm_x4(af[mf][0], af[mf][1], af[mf][2], af[mf][3], addr);
        }
        uint32_t bf[4][2];
        #pragma unroll
        for (int p = 0; p < 2; p++) {
            uint32_t addr = s2u(sB + (wn + p * 16 + b_row_in) * LDT + kc + b_col_in);
            ldsm_x4(bf[2 * p][0], bf[2 * p][1], bf[2 * p + 1][0], bf[2 * p + 1][1], addr);
        }
        #pragma unroll
        for (int mf = 0; mf < 4; mf++)
            #pragma unroll
            for (int nf = 0; nf < 4; nf++)
                mma_16816(acc[mf][nf], af[mf], bf[nf]);
    }

    // Epilogue: bias + sigmoid + float2 stores (col even -> 8B aligned)
    #pragma unroll
    for (int mf = 0; mf < 4; mf++) {
        int r0 = m0 + wm + mf * 16 + (lane >> 2);
        #pragma unroll
        for (int nf = 0; nf < 4; nf++) {
            int col = n0 + wn + nf * 8 + (lane & 3) * 2;
            if (col < NSONGS) {
                float b0 = __ldg(&bias[col]);
                float b1 = __ldg(&bias[col + 1]);
                float2 v0, v1;
                v0.x = sigmoid_fast(acc[mf][nf][0] + b0);
                v0.y = sigmoid_fast(acc[mf][nf][1] + b1);
                v1.x = sigmoid_fast(acc[mf][nf][2] + b0);
                v1.y = sigmoid_fast(acc[mf][nf][3] + b1);
                *(float2*)(out + (size_t)r0 * NSONGS + col) = v0;
                *(float2*)(out + (size_t)(r0 + 8) * NSONGS + col) = v1;
            }
        }
    }
}

// ---------------------------------------------------------------------------
extern "C" void kernel_launch(void* const* d_in, const int* in_sizes, int n_in,
                              void* d_out, int out_size) {
    const int*   songs = (const int*)d_in[0];
    const float* emb   = (const float*)d_in[1];
    const float* W     = (const float*)d_in[2];
    const float* bias  = (const float*)d_in[3];
    float* out = (float*)d_out;

    pool_kernel<<<BATCH / 4, dim3(64, 4)>>>(songs, emb);
    convert_w_kernel<<<(NSONGS * EMBED / 4 + 255) / 256, 256>>>(W);

    dim3 grid(BATCH / BM, (NSONGS + BN - 1) / BN);  // 8 x 782
    gemm_kernel<<<grid, 256>>>(bias, out);
}

// round 2
// speedup vs baseline: 1.3993x; 1.3993x over previous
#include <cuda_runtime.h>
#include <cuda_bf16.h>
#include <cstdint>

#define NSONGS 100000
#define EMBED  64
#define BATCH  1024
#define SEQ    200

#define BM 128
#define BN 128
#define LDT 72   // smem row pitch in bf16 elems (144B) -> conflict-free ldmatrix

// Scratch (no allocations allowed): bf16 W (12.8MB) + bf16 pooled (128KB)
__device__ __nv_bfloat16 g_Wb[(size_t)NSONGS * EMBED];
__device__ __nv_bfloat16 g_pooled[BATCH * EMBED];

// ---------------------------------------------------------------------------
// Kernel 1 (fused): blocks [0,BATCH) do masked-mean pooling (1 sample/block,
// 4-way seq split); blocks [BATCH, BATCH+CONV_BLKS) convert W fp32->bf16.
// ---------------------------------------------------------------------------
#define CONV_PER_THREAD 8   // floats per thread in convert part
#define CONV_BLKS ((NSONGS * EMBED) / (CONV_PER_THREAD * 256))  // 3125

__global__ __launch_bounds__(256) void prep_kernel(const int* __restrict__ songs,
                                                   const float* __restrict__ emb,
                                                   const float* __restrict__ W) {
    const int t = threadIdx.x;
    const int blk = blockIdx.x;

    if (blk < BATCH) {
        // ---- pooling for sample `blk` ----
        __shared__ int s_ids[SEQ];
        __shared__ float s_part[4][EMBED];
        __shared__ int s_cnt;

        if (t == 0) s_cnt = 0;
        __syncthreads();

        const int* srow = songs + blk * SEQ;
        int cnt = 0;
        for (int j = t; j < SEQ; j += 256) {
            int id = srow[j];
            s_ids[j] = id;
            if (id != NSONGS) cnt++;
        }
        cnt = __reduce_add_sync(0xffffffffu, cnt);
        if ((t & 31) == 0 && cnt) atomicAdd(&s_cnt, cnt);
        __syncthreads();

        const int d = t & 63;
        const int s = t >> 6;   // 0..3 seq slice
        float acc = 0.f;
        #pragma unroll 2
        for (int j = s; j < SEQ; j += 4) {
            int id = s_ids[j];
            if (id != NSONGS)
                acc += __ldg(&emb[(size_t)id * EMBED + d]);
        }
        s_part[s][d] = acc;
        __syncthreads();

        if (t < EMBED) {
            float tot = s_part[0][t] + s_part[1][t] + s_part[2][t] + s_part[3][t];
            g_pooled[blk * EMBED + t] = __float2bfloat16(tot / (float)s_cnt);
        }
    } else {
        // ---- W fp32 -> bf16, 8 floats per thread (two float4 -> one uint4) ----
        size_t base = ((size_t)(blk - BATCH) * 256 + t) * CONV_PER_THREAD;
        float4 v0 = *(const float4*)(W + base);
        float4 v1 = *(const float4*)(W + base + 4);
        __nv_bfloat162 p0 = __floats2bfloat162_rn(v0.x, v0.y);
        __nv_bfloat162 p1 = __floats2bfloat162_rn(v0.z, v0.w);
        __nv_bfloat162 p2 = __floats2bfloat162_rn(v1.x, v1.y);
        __nv_bfloat162 p3 = __floats2bfloat162_rn(v1.z, v1.w);
        uint4 o;
        o.x = *(unsigned int*)&p0;
        o.y = *(unsigned int*)&p1;
        o.z = *(unsigned int*)&p2;
        o.w = *(unsigned int*)&p3;
        *(uint4*)(g_Wb + base) = o;
    }
}

// ---------------------------------------------------------------------------
// Kernel 2: GEMM [1024,64]x[64,100000] bf16 mma + bias + poly sigmoid
// ---------------------------------------------------------------------------
__device__ __forceinline__ uint32_t s2u(const void* p) {
    return (uint32_t)__cvta_generic_to_shared(p);
}

__device__ __forceinline__ void ldsm_x4(uint32_t& r0, uint32_t& r1,
                                        uint32_t& r2, uint32_t& r3,
                                        uint32_t addr) {
    asm volatile("ldmatrix.sync.aligned.m8n8.x4.shared.b16 {%0,%1,%2,%3}, [%4];"
                 : "=r"(r0), "=r"(r1), "=r"(r2), "=r"(r3) : "r"(addr));
}

__device__ __forceinline__ void mma_16816(float* c, const uint32_t* a,
                                          const uint32_t* b) {
    asm volatile(
        "mma.sync.aligned.m16n8k16.row.col.f32.bf16.bf16.f32 "
        "{%0,%1,%2,%3},{%4,%5,%6,%7},{%8,%9},{%0,%1,%2,%3};"
        : "+f"(c[0]), "+f"(c[1]), "+f"(c[2]), "+f"(c[3])
        : "r"(a[0]), "r"(a[1]), "r"(a[2]), "r"(a[3]), "r"(b[0]), "r"(b[1]));
}

// Poly sigmoid: 1/2 + x/4 - x^3/48 + x^5/480 - 17x^7/80640, |err|<3e-5 on |x|<=1.
__device__ __forceinline__ float sigmoid_fast(float x) {
    float ax = fabsf(x);
    if (ax < 1.0f) {
        float x2 = x * x;
        return 0.5f + x * (0.25f + x2 * (-2.0833334e-2f +
                     x2 * (2.0833333e-3f + x2 * (-2.1081349e-4f))));
    }
    return 1.0f / (1.0f + __expf(-x));
}

__device__ __forceinline__ void stcs_f2(float* p, float2 v) {
    asm volatile("st.global.cs.v2.f32 [%0], {%1,%2};" :: "l"(p), "f"(v.x), "f"(v.y)
                 : "memory");
}

__global__ __launch_bounds__(256) void gemm_kernel(const float* __restrict__ bias,
                                                   float* __restrict__ out) {
    __shared__ __nv_bfloat16 sA[BM * LDT];
    __shared__ __nv_bfloat16 sB[BN * LDT];

    const int tid = threadIdx.x;
    const int m0 = blockIdx.x * BM;
    const int n0 = blockIdx.y * BN;

    // Cooperative loads: each thread moves 4x 16B chunks for A and B.
    {
        int r = tid >> 3;          // 0..31
        int c = (tid & 7) * 8;     // 0..56 (bf16 elems)
        #pragma unroll
        for (int i = 0; i < 4; i++) {
            int row = r + i * 32;
            uint4 v = *(const uint4*)(g_pooled + (m0 + row) * EMBED + c);
            *(uint4*)(sA + row * LDT + c) = v;
        }
        #pragma unroll
        for (int i = 0; i < 4; i++) {
            int row = r + i * 32;
            int n = n0 + row;
            uint4 v = make_uint4(0u, 0u, 0u, 0u);
            if (n < NSONGS)
                v = *(const uint4*)(g_Wb + (size_t)n * EMBED + c);
            *(uint4*)(sB + row * LDT + c) = v;
        }
    }

    const int warp = tid >> 5;
    const int lane = tid & 31;
    const int wm = (warp >> 2) * 64;   // 0 or 64
    const int wn = (warp & 3) * 32;    // 0,32,64,96

    // Hoist bias loads: 8 values per thread (col depends on nf & lane only),
    // issued here so their latency hides under ldmatrix+mma below.
    float bv0[4], bv1[4];
    #pragma unroll
    for (int nf = 0; nf < 4; nf++) {
        int col = n0 + wn + nf * 8 + (lane & 3) * 2;
        if (col < NSONGS) {
            bv0[nf] = __ldg(&bias[col]);
            bv1[nf] = __ldg(&bias[col + 1]);
        } else { bv0[nf] = 0.f; bv1[nf] = 0.f; }
    }

    __syncthreads();

    float acc[4][4][4];
    #pragma unroll
    for (int mf = 0; mf < 4; mf++)
        #pragma unroll
        for (int nf = 0; nf < 4; nf++)
            #pragma unroll
            for (int i = 0; i < 4; i++) acc[mf][nf][i] = 0.f;

    // Per-lane ldmatrix address components
    const int a_row_in = (lane & 7) + ((lane >> 3) & 1) * 8; // row within 16
    const int a_col_in = (lane >> 4) * 8;                    // 0 or 8
    const int b_g = lane >> 3;
    const int b_row_in = (lane & 7) + (b_g >> 1) * 8;
    const int b_col_in = (b_g & 1) * 8;

    #pragma unroll
    for (int ks = 0; ks < 4; ks++) {
        const int kc = ks * 16;
        uint32_t af[4][4];
        #pragma unroll
        for (int mf = 0; mf < 4; mf++) {
            uint32_t addr = s2u(sA + (wm + mf * 16 + a_row_in) * LDT + kc + a_col_in);
            ldsm_x4(af[mf][0], af[mf][1], af[mf][2], af[mf][3], addr);
        }
        uint32_t bf[4][2];
        #pragma unroll
        for (int p = 0; p < 2; p++) {
            uint32_t addr = s2u(sB + (wn + p * 16 + b_row_in) * LDT + kc + b_col_in);
            ldsm_x4(bf[2 * p][0], bf[2 * p][1], bf[2 * p + 1][0], bf[2 * p + 1][1], addr);
        }
        #pragma unroll
        for (int mf = 0; mf < 4; mf++)
            #pragma unroll
            for (int nf = 0; nf < 4; nf++)
                mma_16816(acc[mf][nf], af[mf], bf[nf]);
    }

    // Epilogue: bias + sigmoid + streaming float2 stores
    #pragma unroll
    for (int mf = 0; mf < 4; mf++) {
        int r0 = m0 + wm + mf * 16 + (lane >> 2);
        #pragma unroll
        for (int nf = 0; nf < 4; nf++) {
            int col = n0 + wn + nf * 8 + (lane & 3) * 2;
            if (col < NSONGS) {
                float2 v0, v1;
                v0.x = sigmoid_fast(acc[mf][nf][0] + bv0[nf]);
                v0.y = sigmoid_fast(acc[mf][nf][1] + bv1[nf]);
                v1.x = sigmoid_fast(acc[mf][nf][2] + bv0[nf]);
                v1.y = sigmoid_fast(acc[mf][nf][3] + bv1[nf]);
                stcs_f2(out + (size_t)r0 * NSONGS + col, v0);
                stcs_f2(out + (size_t)(r0 + 8) * NSONGS + col, v1);
            }
        }
    }
}

// ---------------------------------------------------------------------------
extern "C" void kernel_launch(void* const* d_in, const int* in_sizes, int n_in,
                              void* d_out, int out_size) {
    const int*   songs = (const int*)d_in[0];
    const float* emb   = (const float*)d_in[1];
    const float* W     = (const float*)d_in[2];
    const float* bias  = (const float*)d_in[3];
    float* out = (float*)d_out;

    prep_kernel<<<BATCH + CONV_BLKS, 256>>>(songs, emb, W);

    dim3 grid(BATCH / BM, (NSONGS + BN - 1) / BN);  // 8 x 782
    gemm_kernel<<<grid, 256>>>(bias, out);
}

// round 3
// speedup vs baseline: 1.5390x; 1.0999x over previous
#include <cuda_runtime.h>
#include <cuda_bf16.h>
#include <cstdint>

#define NSONGS 100000
#define EMBED  64
#define BATCH  1024
#define SEQ    200

#define BM 64
#define BN 128
#define LDT 72   // smem row pitch in bf16 elems (144B) -> conflict-free ldmatrix

// Scratch (no allocations allowed): bf16 W (12.8MB) + bf16 pooled (128KB)
__device__ __nv_bfloat16 g_Wb[(size_t)NSONGS * EMBED];
__device__ __nv_bfloat16 g_pooled[BATCH * EMBED];

// ---------------------------------------------------------------------------
// Kernel 1 (fused): blocks [0,BATCH) do masked-mean pooling (1 sample/block,
// 4-way seq split); blocks [BATCH, BATCH+CONV_BLKS) convert W fp32->bf16.
// ---------------------------------------------------------------------------
#define CONV_PER_THREAD 8
#define CONV_BLKS ((NSONGS * EMBED) / (CONV_PER_THREAD * 256))  // 3125

__global__ __launch_bounds__(256) void prep_kernel(const int* __restrict__ songs,
                                                   const float* __restrict__ emb,
                                                   const float* __restrict__ W) {
    const int t = threadIdx.x;
    const int blk = blockIdx.x;

    if (blk < BATCH) {
        __shared__ int s_ids[SEQ];
        __shared__ float s_part[4][EMBED];
        __shared__ int s_cnt;

        if (t == 0) s_cnt = 0;
        __syncthreads();

        const int* srow = songs + blk * SEQ;
        int cnt = 0;
        for (int j = t; j < SEQ; j += 256) {
            int id = srow[j];
            s_ids[j] = id;
            if (id != NSONGS) cnt++;
        }
        cnt = __reduce_add_sync(0xffffffffu, cnt);
        if ((t & 31) == 0 && cnt) atomicAdd(&s_cnt, cnt);
        __syncthreads();

        const int d = t & 63;
        const int s = t >> 6;
        float acc = 0.f;
        #pragma unroll 2
        for (int j = s; j < SEQ; j += 4) {
            int id = s_ids[j];
            if (id != NSONGS)
                acc += __ldg(&emb[(size_t)id * EMBED + d]);
        }
        s_part[s][d] = acc;
        __syncthreads();

        if (t < EMBED) {
            float tot = s_part[0][t] + s_part[1][t] + s_part[2][t] + s_part[3][t];
            g_pooled[blk * EMBED + t] = __float2bfloat16(tot / (float)s_cnt);
        }
    } else {
        size_t base = ((size_t)(blk - BATCH) * 256 + t) * CONV_PER_THREAD;
        float4 v0 = *(const float4*)(W + base);
        float4 v1 = *(const float4*)(W + base + 4);
        __nv_bfloat162 p0 = __floats2bfloat162_rn(v0.x, v0.y);
        __nv_bfloat162 p1 = __floats2bfloat162_rn(v0.z, v0.w);
        __nv_bfloat162 p2 = __floats2bfloat162_rn(v1.x, v1.y);
        __nv_bfloat162 p3 = __floats2bfloat162_rn(v1.z, v1.w);
        uint4 o;
        o.x = *(unsigned int*)&p0;
        o.y = *(unsigned int*)&p1;
        o.z = *(unsigned int*)&p2;
        o.w = *(unsigned int*)&p3;
        *(uint4*)(g_Wb + base) = o;
    }
}

// ---------------------------------------------------------------------------
// Kernel 2: GEMM [1024,64]x[64,100000] bf16 mma + bias + packed-f32x2 sigmoid
// ---------------------------------------------------------------------------
typedef unsigned long long u64;

__device__ __forceinline__ uint32_t s2u(const void* p) {
    return (uint32_t)__cvta_generic_to_shared(p);
}

__device__ __forceinline__ void ldsm_x4(uint32_t& r0, uint32_t& r1,
                                        uint32_t& r2, uint32_t& r3,
                                        uint32_t addr) {
    asm volatile("ldmatrix.sync.aligned.m8n8.x4.shared.b16 {%0,%1,%2,%3}, [%4];"
                 : "=r"(r0), "=r"(r1), "=r"(r2), "=r"(r3) : "r"(addr));
}

__device__ __forceinline__ void mma_16816(float* c, const uint32_t* a,
                                          const uint32_t* b) {
    asm volatile(
        "mma.sync.aligned.m16n8k16.row.col.f32.bf16.bf16.f32 "
        "{%0,%1,%2,%3},{%4,%5,%6,%7},{%8,%9},{%0,%1,%2,%3};"
        : "+f"(c[0]), "+f"(c[1]), "+f"(c[2]), "+f"(c[3])
        : "r"(a[0]), "r"(a[1]), "r"(a[2]), "r"(a[3]), "r"(b[0]), "r"(b[1]));
}

// ---- packed f32x2 helpers (Blackwell FFMA2 path) ----
__device__ __forceinline__ u64 pk2(float a, float b) {
    u64 r; asm("mov.b64 %0,{%1,%2};" : "=l"(r) : "f"(a), "f"(b)); return r;
}
__device__ __forceinline__ void upk2(float& a, float& b, u64 v) {
    asm("mov.b64 {%0,%1},%2;" : "=f"(a), "=f"(b) : "l"(v));
}
__device__ __forceinline__ u64 add2(u64 a, u64 b) {
    u64 d; asm("add.rn.f32x2 %0,%1,%2;" : "=l"(d) : "l"(a), "l"(b)); return d;
}
__device__ __forceinline__ u64 mul2(u64 a, u64 b) {
    u64 d; asm("mul.rn.f32x2 %0,%1,%2;" : "=l"(d) : "l"(a), "l"(b)); return d;
}
__device__ __forceinline__ u64 fma2(u64 a, u64 b, u64 c) {
    u64 d; asm("fma.rn.f32x2 %0,%1,%2,%3;" : "=l"(d) : "l"(a), "l"(b), "l"(c)); return d;
}
__device__ __forceinline__ void st_cs_b64(float* p, u64 v) {
    asm volatile("st.global.cs.b64 [%0], %1;" :: "l"(p), "l"(v) : "memory");
}

__device__ __forceinline__ float sigmoid_ref(float x) {
    return 1.0f / (1.0f + __expf(-x));
}

// sigmoid on a packed pair; poly valid |x|<1 (|err|<3e-5), scalar fallback else.
__device__ __forceinline__ u64 sigmoid2(u64 x, u64 C7, u64 C5, u64 C3,
                                        u64 C1, u64 CH) {
    u64 x2 = mul2(x, x);
    u64 t = fma2(x2, C7, C5);
    t = fma2(x2, t, C3);
    t = fma2(x2, t, C1);
    u64 r = fma2(x, t, CH);
    float x0, x1;
    upk2(x0, x1, x);
    if (fmaxf(fabsf(x0), fabsf(x1)) >= 1.0f)
        r = pk2(sigmoid_ref(x0), sigmoid_ref(x1));
    return r;
}

__global__ __launch_bounds__(256, 3) void gemm_kernel(const float* __restrict__ bias,
                                                      float* __restrict__ out) {
    __shared__ __nv_bfloat16 sA[BM * LDT];
    __shared__ __nv_bfloat16 sB[BN * LDT];

    const int tid = threadIdx.x;
    const int m0 = blockIdx.x * BM;
    const int n0 = blockIdx.y * BN;

    // Cooperative loads
    {
        int r = tid >> 3;          // 0..31
        int c = (tid & 7) * 8;     // 0..56
        #pragma unroll
        for (int i = 0; i < 2; i++) {
            int row = r + i * 32;
            uint4 v = *(const uint4*)(g_pooled + (m0 + row) * EMBED + c);
            *(uint4*)(sA + row * LDT + c) = v;
        }
        #pragma unroll
        for (int i = 0; i < 4; i++) {
            int row = r + i * 32;
            int n = n0 + row;
            uint4 v = make_uint4(0u, 0u, 0u, 0u);
            if (n < NSONGS)
                v = *(const uint4*)(g_Wb + (size_t)n * EMBED + c);
            *(uint4*)(sB + row * LDT + c) = v;
        }
    }

    const int warp = tid >> 5;
    const int lane = tid & 31;
    const int wm = (warp >> 2) * 32;   // 0 or 32
    const int wn = (warp & 3) * 32;    // 0,32,64,96

    // Hoisted bias (packed pairs), issued before the sync/MMA to hide latency.
    u64 bvp[4];
    #pragma unroll
    for (int nf = 0; nf < 4; nf++) {
        int col = n0 + wn + nf * 8 + (lane & 3) * 2;
        float b0 = 0.f, b1 = 0.f;
        if (col < NSONGS) { b0 = __ldg(&bias[col]); b1 = __ldg(&bias[col + 1]); }
        bvp[nf] = pk2(b0, b1);
    }

    __syncthreads();

    float acc[2][4][4];
    #pragma unroll
    for (int mf = 0; mf < 2; mf++)
        #pragma unroll
        for (int nf = 0; nf < 4; nf++)
            #pragma unroll
            for (int i = 0; i < 4; i++) acc[mf][nf][i] = 0.f;

    const int a_row_in = (lane & 7) + ((lane >> 3) & 1) * 8;
    const int a_col_in = (lane >> 4) * 8;
    const int b_g = lane >> 3;
    const int b_row_in = (lane & 7) + (b_g >> 1) * 8;
    const int b_col_in = (b_g & 1) * 8;

    #pragma unroll
    for (int ks = 0; ks < 4; ks++) {
        const int kc = ks * 16;
        uint32_t af[2][4];
        #pragma unroll
        for (int mf = 0; mf < 2; mf++) {
            uint32_t addr = s2u(sA + (wm + mf * 16 + a_row_in) * LDT + kc + a_col_in);
            ldsm_x4(af[mf][0], af[mf][1], af[mf][2], af[mf][3], addr);
        }
        uint32_t bf[4][2];
        #pragma unroll
        for (int p = 0; p < 2; p++) {
            uint32_t addr = s2u(sB + (wn + p * 16 + b_row_in) * LDT + kc + b_col_in);
            ldsm_x4(bf[2 * p][0], bf[2 * p][1], bf[2 * p + 1][0], bf[2 * p + 1][1], addr);
        }
        #pragma unroll
        for (int mf = 0; mf < 2; mf++)
            #pragma unroll
            for (int nf = 0; nf < 4; nf++)
                mma_16816(acc[mf][nf], af[mf], bf[nf]);
    }

    // Packed-constant setup (hoisted, 5 movs)
    const u64 C7 = pk2(-2.1081349e-4f, -2.1081349e-4f);
    const u64 C5 = pk2( 2.0833333e-3f,  2.0833333e-3f);
    const u64 C3 = pk2(-2.0833334e-2f, -2.0833334e-2f);
    const u64 C1 = pk2( 0.25f, 0.25f);
    const u64 CH = pk2( 0.5f, 0.5f);

    // Epilogue: one base pointer, constant offsets -> STG immediates.
    const int col_l = (lane & 3) * 2;
    float* base = out + (size_t)(m0 + wm + (lane >> 2)) * NSONGS + n0 + wn + col_l;
    const bool full = (n0 + BN) <= NSONGS;   // whole tile in-bounds (true for all but last n-block)

    #pragma unroll
    for (int mf = 0; mf < 2; mf++) {
        float* bm = base + mf * 16 * NSONGS;
        #pragma unroll
        for (int nf = 0; nf < 4; nf++) {
            if (full || (n0 + wn + nf * 8 + col_l) < NSONGS) {
                u64 x0 = add2(pk2(acc[mf][nf][0], acc[mf][nf][1]), bvp[nf]);
                u64 x1 = add2(pk2(acc[mf][nf][2], acc[mf][nf][3]), bvp[nf]);
                st_cs_b64(bm + nf * 8, sigmoid2(x0, C7, C5, C3, C1, CH));
                st_cs_b64(bm + 8 * NSONGS + nf * 8, sigmoid2(x1, C7, C5, C3, C1, CH));
            }
        }
    }
}

// ---------------------------------------------------------------------------
extern "C" void kernel_launch(void* const* d_in, const int* in_sizes, int n_in,
                              void* d_out, int out_size) {
    const int*   songs = (const int*)d_in[0];
    const float* emb   = (const float*)d_in[1];
    const float* W     = (const float*)d_in[2];
    const float* bias  = (const float*)d_in[3];
    float* out = (float*)d_out;

    prep_kernel<<<BATCH + CONV_BLKS, 256>>>(songs, emb, W);

    dim3 grid(BATCH / BM, (NSONGS + BN - 1) / BN);  // 16 x 782
    gemm_kernel<<<grid, 256>>>(bias, out);
}